// round 9
// baseline (speedup 1.0000x reference)
#include <cuda_runtime.h>
#include <cstdint>

// GROUND TRUTH (R8 dump): n_in=5, sizes = 16777216, 32768, 32768, 512, 1
//   d_in[0] inputs        [B,K,D] fp32,  B=8, K=4096, D=512
//   d_in[1] mask_ids      [B,M]   int32, M=4096
//   d_in[2] keep_ids      [B,K]   int32
//   d_in[3] mask_emb      [D]     fp32
//   d_in[4] axis          scalar  (ignored)
//   out  [B, L=8192, D] fp32  (33,554,432 elements)
//
// out[b, keep_ids[b,k], :] = inputs[b,k,:]
// out[b, mask_ids[b,m], :] = mask_embedding
// keep ∪ mask ids tile [0,L) per batch -> every output row written once.

#define B_ 8
#define K_ 4096
#define M_ 4096
#define L_ (K_ + M_)   // 8192
#define D_ 512

__global__ __launch_bounds__(128, 16)
void maskfiller_scatter_kernel(const float* __restrict__ inputs,   // [B,K,D]
                               const int*   __restrict__ mask_ids, // [B,M]
                               const int*   __restrict__ keep_ids, // [B,K]
                               const float* __restrict__ mask_emb, // [D]
                               float*       __restrict__ out)      // [B,L,D]
{
    const int r = blockIdx.x;          // [0, B*L)
    const int b = r >> 13;             // / 8192
    const int i = r & (L_ - 1);        // % 8192
    const int t = threadIdx.x;         // 0..127, one float4 each

    float4 v;
    int dst_row;
    if (i < K_) {
        // keep row: copy inputs[b,i,:]
        dst_row = keep_ids[b * K_ + i];
        const float4* src = reinterpret_cast<const float4*>(inputs + ((size_t)(b * K_ + i)) * D_);
        v = src[t];
    } else {
        // mask row: broadcast embedding (2KB, L2-resident)
        dst_row = mask_ids[b * M_ + (i - K_)];
        const float4* src = reinterpret_cast<const float4*>(mask_emb);
        v = src[t];
    }

    float4* dst = reinterpret_cast<float4*>(out + ((size_t)b * L_ + dst_row) * D_);
    dst[t] = v;
}

extern "C" void kernel_launch(void* const* d_in, const int* in_sizes, int n_in,
                              void* d_out, int out_size)
{
    const float* inputs   = (const float*)d_in[0];
    const int*   mask_ids = (const int*)  d_in[1];
    const int*   keep_ids = (const int*)  d_in[2];
    const float* mask_emb = (const float*)d_in[3];
    float*       out      = (float*)d_out;
    (void)in_sizes; (void)n_in; (void)out_size;

    maskfiller_scatter_kernel<<<B_ * L_, 128>>>(inputs, mask_ids, keep_ids, mask_emb, out);
}

// round 11
// speedup vs baseline: 1.1291x; 1.1291x over previous
#include <cuda_runtime.h>
#include <cstdint>

// Interface (R8 ground truth): n_in=5, sizes = 16777216, 32768, 32768, 512, 1
//   d_in[0] inputs   [B=8, K=4096, D=512] fp32
//   d_in[1] mask_ids [B, M=4096] int32
//   d_in[2] keep_ids [B, K=4096] int32
//   d_in[3] mask_emb [D=512] fp32
//   d_in[4] axis (ignored)
//   out [B, L=8192, D] fp32
//
// out[b, keep_ids[b,k], :] = inputs[b,k,:]
// out[b, mask_ids[b,m], :] = mask_embedding
//
// R9 profile: DRAM 47.7%, issue 19% -> latency-bound, MLP=1/thread.
// This version: 256-thread CTAs, 8 rows/CTA, 4 independent float4 copies
// per thread. K and M divisible by 8 -> each CTA uniformly keep- or
// mask-typed (uniform branch). Streaming hints (__ldcs/__stcs) keep the
// 128MB write stream from thrashing L2.
// (R10 bench was an infra failure; re-running this design.)

#define B_ 8
#define K_ 4096
#define M_ 4096
#define L_ (K_ + M_)      // 8192
#define D_ 512
#define V_ (D_ / 4)       // 128 float4 per row
#define RPC 8             // rows per CTA

__global__ __launch_bounds__(256, 8)
void maskfiller_scatter8_kernel(const float4* __restrict__ inputs,   // [B*K, 128]
                                const int*    __restrict__ mask_ids, // [B,M]
                                const int*    __restrict__ keep_ids, // [B,K]
                                const float4* __restrict__ mask_emb, // [128]
                                float4*       __restrict__ out)      // [B*L, 128]
{
    const int r0 = blockIdx.x << 3;        // first of 8 global rows
    const int b  = r0 >> 13;               // batch (L=8192)
    const int i0 = r0 & (L_ - 1);          // row-in-batch of first row
    const int t  = threadIdx.x;
    const int j  = t & (V_ - 1);           // float4 column 0..127
    const int rs = t >> 7;                 // row sub-slot 0/1

    const size_t out_base = (size_t)b * L_;

    if (i0 < K_) {
        // ---- keep CTA: copy 8 rows of inputs to scattered out rows ----
        int ids[4];
        float4 v[4];
        const int kbase = b * K_ + i0 + rs;
        #pragma unroll
        for (int u = 0; u < 4; ++u)
            ids[u] = __ldg(&keep_ids[kbase + 2 * u]);
        #pragma unroll
        for (int u = 0; u < 4; ++u)
            v[u] = __ldcs(&inputs[(size_t)(kbase + 2 * u) * V_ + j]);
        #pragma unroll
        for (int u = 0; u < 4; ++u)
            __stcs(&out[(out_base + ids[u]) * V_ + j], v[u]);
    } else {
        // ---- mask CTA: broadcast embedding to 8 scattered out rows ----
        const int mbase = b * M_ + (i0 - K_) + rs;
        const float4 v = __ldg(&mask_emb[j]);
        int ids[4];
        #pragma unroll
        for (int u = 0; u < 4; ++u)
            ids[u] = __ldg(&mask_ids[mbase + 2 * u]);
        #pragma unroll
        for (int u = 0; u < 4; ++u)
            __stcs(&out[(out_base + ids[u]) * V_ + j], v);
    }
}

extern "C" void kernel_launch(void* const* d_in, const int* in_sizes, int n_in,
                              void* d_out, int out_size)
{
    const float4* inputs   = (const float4*)d_in[0];
    const int*    mask_ids = (const int*)   d_in[1];
    const int*    keep_ids = (const int*)   d_in[2];
    const float4* mask_emb = (const float4*)d_in[3];
    float4*       out      = (float4*)d_out;
    (void)in_sizes; (void)n_in; (void)out_size;

    maskfiller_scatter8_kernel<<<(B_ * L_) / RPC, 256>>>(inputs, mask_ids, keep_ids, mask_emb, out);
}

// round 12
// speedup vs baseline: 1.1803x; 1.0453x over previous
#include <cuda_runtime.h>
#include <cstdint>

// Interface (R8 ground truth): n_in=5, sizes = 16777216, 32768, 32768, 512, 1
//   d_in[0] inputs   [B=8, K=4096, D=512] fp32
//   d_in[1] mask_ids [B, M=4096] int32
//   d_in[2] keep_ids [B, K=4096] int32
//   d_in[3] mask_emb [D=512] fp32
//   d_in[4] axis (ignored)
//   out [B, L=8192, D] fp32
//
// R11 profile: dur 33.9us, DRAM 53.3%, L1 69.8%, issue 20% -> still
// latency-exposed. This version: 16 rows/CTA, 256 threads, 8 independent
// float4 copies per thread (MLP 8). CTAs remain uniformly keep- or
// mask-typed (K, M divisible by 16). Streaming hints keep the 128MB
// write-once stream out of L2's way.

#define B_ 8
#define K_ 4096
#define M_ 4096
#define L_ (K_ + M_)      // 8192
#define D_ 512
#define V_ (D_ / 4)       // 128 float4 per row
#define RPC 16            // rows per CTA

__global__ __launch_bounds__(256, 4)
void maskfiller_scatter16_kernel(const float4* __restrict__ inputs,   // [B*K, 128]
                                 const int*    __restrict__ mask_ids, // [B,M]
                                 const int*    __restrict__ keep_ids, // [B,K]
                                 const float4* __restrict__ mask_emb, // [128]
                                 float4*       __restrict__ out)      // [B*L, 128]
{
    const int r0 = blockIdx.x * RPC;       // first of 16 global rows
    const int b  = r0 >> 13;               // batch (L=8192)
    const int i0 = r0 & (L_ - 1);          // row-in-batch of first row
    const int t  = threadIdx.x;
    const int j  = t & (V_ - 1);           // float4 column 0..127
    const int rs = t >> 7;                 // row sub-slot 0/1

    const size_t out_base = (size_t)b * L_;

    if (i0 < K_) {
        // ---- keep CTA: copy 16 rows of inputs to scattered out rows ----
        const int kbase = b * K_ + i0 + rs;
        int ids[8];
        float4 v[8];
        #pragma unroll
        for (int u = 0; u < 8; ++u)
            ids[u] = __ldg(&keep_ids[kbase + 2 * u]);
        #pragma unroll
        for (int u = 0; u < 8; ++u)
            v[u] = __ldcs(&inputs[(size_t)(kbase + 2 * u) * V_ + j]);
        #pragma unroll
        for (int u = 0; u < 8; ++u)
            __stcs(&out[(out_base + ids[u]) * V_ + j], v[u]);
    } else {
        // ---- mask CTA: broadcast embedding to 16 scattered out rows ----
        const int mbase = b * M_ + (i0 - K_) + rs;
        const float4 v = __ldg(&mask_emb[j]);
        int ids[8];
        #pragma unroll
        for (int u = 0; u < 8; ++u)
            ids[u] = __ldg(&mask_ids[mbase + 2 * u]);
        #pragma unroll
        for (int u = 0; u < 8; ++u)
            __stcs(&out[(out_base + ids[u]) * V_ + j], v);
    }
}

extern "C" void kernel_launch(void* const* d_in, const int* in_sizes, int n_in,
                              void* d_out, int out_size)
{
    const float4* inputs   = (const float4*)d_in[0];
    const int*    mask_ids = (const int*)   d_in[1];
    const int*    keep_ids = (const int*)   d_in[2];
    const float4* mask_emb = (const float4*)d_in[3];
    float4*       out      = (float4*)d_out;
    (void)in_sizes; (void)n_in; (void)out_size;

    maskfiller_scatter16_kernel<<<(B_ * L_) / RPC, 256>>>(inputs, mask_ids, keep_ids, mask_emb, out);
}

// round 13
// speedup vs baseline: 1.1813x; 1.0009x over previous
#include <cuda_runtime.h>
#include <cstdint>

// Interface (R8 ground truth): n_in=5, sizes = 16777216, 32768, 32768, 512, 1
//   d_in[0] inputs   [B=8, K=4096, D=512] fp32
//   d_in[1] mask_ids [B, M=4096] int32
//   d_in[2] keep_ids [B, K=4096] int32
//   d_in[3] mask_emb [D=512] fp32
//   out [B, L=8192, D] fp32
//
// R12: register file caps in-flight float4 at ~8K/SM -> DRAM stuck at 64%.
// This version uses cp.async.bulk (register-free async copies):
//   keep CTA: 1x bulk 32KB gmem->smem (16 contiguous input rows),
//             then 16x bulk 2KB smem->gmem scattered row stores.
//   mask CTA: stage 2KB embedding in smem, 16x bulk 2KB stores.
// In-flight bytes/SM ~ 224KB (7 CTAs x 32KB) >> register-path depth.

#define B_ 8
#define K_ 4096
#define M_ 4096
#define L_ (K_ + M_)      // 8192
#define D_ 512
#define ROW_BYTES (D_ * 4)   // 2048
#define RPC 16               // rows per CTA
#define TILE_BYTES (RPC * ROW_BYTES)  // 32768

__device__ __forceinline__ unsigned smem_u32(const void* p)
{
    unsigned a;
    asm("{ .reg .u64 t; cvta.to.shared.u64 t, %1; cvt.u32.u64 %0, t; }"
        : "=r"(a) : "l"(p));
    return a;
}

__global__ __launch_bounds__(128, 1)
void maskfiller_bulk_kernel(const float* __restrict__ inputs,   // [B*K, D]
                            const int*   __restrict__ mask_ids, // [B,M]
                            const int*   __restrict__ keep_ids, // [B,K]
                            const float* __restrict__ mask_emb, // [D]
                            float*       __restrict__ out)      // [B*L, D]
{
    __shared__ alignas(128) char buf[TILE_BYTES];
    __shared__ alignas(8) unsigned long long mbar;
    __shared__ int ids[RPC];

    const int r0 = blockIdx.x * RPC;     // first of 16 global rows
    const int b  = r0 >> 13;             // batch (L = 8192)
    const int i0 = r0 & (L_ - 1);        // row-in-batch
    const int t  = threadIdx.x;
    const bool keep = (i0 < K_);

    const unsigned mbar_a = smem_u32(&mbar);
    const unsigned buf_a  = smem_u32(buf);

    if (t == 0) {
        asm volatile("mbarrier.init.shared.b64 [%0], 1;" :: "r"(mbar_a) : "memory");
        asm volatile("fence.proxy.async.shared::cta;" ::: "memory");
    }
    __syncthreads();   // mbar visible to all / to async proxy

    if (keep) {
        // Kick the 32KB contiguous bulk load first (thread 0).
        if (t == 0) {
            const float* src = inputs + (size_t)(b * K_ + i0) * D_;
            asm volatile(
                "mbarrier.arrive.expect_tx.shared.b64 _, [%0], %1;"
                :: "r"(mbar_a), "r"((unsigned)TILE_BYTES) : "memory");
            asm volatile(
                "cp.async.bulk.shared::cta.global.mbarrier::complete_tx::bytes "
                "[%0], [%1], %2, [%3];"
                :: "r"(buf_a), "l"(src), "r"((unsigned)TILE_BYTES), "r"(mbar_a)
                : "memory");
        }
        // Meanwhile fetch the 16 destination ids.
        if (t < RPC) ids[t] = __ldg(&keep_ids[b * K_ + i0 + t]);
        __syncthreads();   // ids ready

        if (t == 0) {
            // Wait for the bulk load to land.
            asm volatile(
                "{\n\t.reg .pred p;\n"
                "W0:\n\t"
                "mbarrier.try_wait.parity.shared::cta.b64 p, [%0], 0;\n\t"
                "@!p bra W0;\n\t}"
                :: "r"(mbar_a) : "memory");
            // 16 scattered 2KB bulk stores.
            const size_t out_base = (size_t)b * L_;
            #pragma unroll
            for (int r = 0; r < RPC; ++r) {
                float* dst = out + (out_base + ids[r]) * D_;
                asm volatile(
                    "cp.async.bulk.global.shared::cta.bulk_group [%0], [%1], %2;"
                    :: "l"(dst), "r"(buf_a + r * ROW_BYTES), "r"((unsigned)ROW_BYTES)
                    : "memory");
            }
            asm volatile("cp.async.bulk.commit_group;" ::: "memory");
            asm volatile("cp.async.bulk.wait_group 0;" ::: "memory");
        }
    } else {
        // Stage the 2KB embedding into smem (128 threads x 1 float4).
        ((float4*)buf)[t] = __ldg(&((const float4*)mask_emb)[t]);
        if (t < RPC) ids[t] = __ldg(&mask_ids[b * M_ + (i0 - K_) + t]);
        __syncthreads();

        if (t == 0) {
            asm volatile("fence.proxy.async.shared::cta;" ::: "memory");
            const size_t out_base = (size_t)b * L_;
            #pragma unroll
            for (int r = 0; r < RPC; ++r) {
                float* dst = out + (out_base + ids[r]) * D_;
                asm volatile(
                    "cp.async.bulk.global.shared::cta.bulk_group [%0], [%1], %2;"
                    :: "l"(dst), "r"(buf_a), "r"((unsigned)ROW_BYTES)
                    : "memory");
            }
            asm volatile("cp.async.bulk.commit_group;" ::: "memory");
            asm volatile("cp.async.bulk.wait_group 0;" ::: "memory");
        }
    }
}

extern "C" void kernel_launch(void* const* d_in, const int* in_sizes, int n_in,
                              void* d_out, int out_size)
{
    const float* inputs   = (const float*)d_in[0];
    const int*   mask_ids = (const int*)  d_in[1];
    const int*   keep_ids = (const int*)  d_in[2];
    const float* mask_emb = (const float*)d_in[3];
    float*       out      = (float*)d_out;
    (void)in_sizes; (void)n_in; (void)out_size;

    maskfiller_bulk_kernel<<<(B_ * L_) / RPC, 128>>>(inputs, mask_ids, keep_ids, mask_emb, out);
}